// round 16
// baseline (speedup 1.0000x reference)
#include <cuda_runtime.h>
#include <cuda_bf16.h>
#include <cstdint>

// Problem constants (from reference)
#define V_SZ     32000
#define D_SZ     5120
#define T_SZ     32
#define B_SZ     4
#define S_SZ     2048
#define VIS_DIM  768
#define N_SHARED (V_SZ + 2)            // 32002
#define NTOK     (B_SZ * S_SZ)         // 8192

// ---------------- K1 gather (TMA ring) — proven 49.7us config ----------
#define THREADS      256
#define ROW_BYTES    (D_SZ * 4)        // 20480 B per row
#define NS           6
#define LOOKAHEAD    4
#define SMEM_BYTES   (128 + NS * ROW_BYTES)   // 123008
#define GRID_GATHER  148
#define TOK_PER_BLK  56

// ---------------- K2/K3 vision ----------------------------------------
#define NCH2         10                // col chunks of 512 (float2/thread)
#define CCOLS        512
#define KS           8                 // k segments of 96
#define KSEG2        (VIS_DIM / KS)    // 96
#define MAXS         128               // max vision tokens processed
#define MAXT         8                 // tokens per register pass
#define K3_SLOTS     8

// Per-gather-block vision lists (pure overwrites, replay-safe, no atomics)
__device__ int g_bcnt[GRID_GATHER];
__device__ int g_list[GRID_GATHER * TOK_PER_BLK];
// Partial projections: [kseg][slot][D] — overwrite semantics, no zeroing
__device__ float g_part[(size_t)KS * MAXS * D_SZ];   // ~21 MB

// ---------------------------------------------------------------------------
// K1: TMA bulk-copy gather of shared-vocab rows; records vision tokens in
// this block's private list slot.
// ---------------------------------------------------------------------------
__global__ __launch_bounds__(THREADS)
void gather_tma_kernel(const int*   __restrict__ text,
                       const float* __restrict__ weight,
                       const float* __restrict__ fig,
                       float*       __restrict__ out)
{
    extern __shared__ __align__(128) char dsmem[];
    __shared__ int s_ids[TOK_PER_BLK];
    __shared__ int s_list[TOK_PER_BLK];

    const int t0 = blockIdx.x * TOK_PER_BLK;
    const int n  = min(TOK_PER_BLK, NTOK - t0);
    const int tid = threadIdx.x;

    if (n <= 0) { if (tid == 0) g_bcnt[blockIdx.x] = 0; return; }

    for (int i = tid; i < n; i += THREADS) s_ids[i] = __ldg(&text[t0 + i]);
    __syncthreads();

    if (tid != 0) return;

    int m = 0, v = 0;
    for (int i = 0; i < n; i++) {
        if (s_ids[i] < N_SHARED) s_list[m++] = i;
        else                     g_list[blockIdx.x * TOK_PER_BLK + (v++)] = t0 + i;
    }
    g_bcnt[blockIdx.x] = v;
    if (m == 0) return;

    uint32_t smem_base;
    asm("{ .reg .u64 t; cvta.to.shared.u64 t, %1; cvt.u32.u64 %0, t; }"
        : "=r"(smem_base) : "l"(dsmem));
    const uint32_t mbar0 = smem_base;
    const uint32_t buf0  = smem_base + 128;

    #pragma unroll
    for (int s = 0; s < NS; s++)
        asm volatile("mbarrier.init.shared.b64 [%0], 1;"
                     :: "r"(mbar0 + s * 8) : "memory");
    asm volatile("fence.proxy.async.shared::cta;" ::: "memory");

    auto src_of = [&](int j) -> const char* {
        int id = s_ids[s_list[j]];
        if (id < V_SZ) return (const char*)(weight + (size_t)id * D_SZ);
        return (const char*)(fig + (size_t)(id - V_SZ) * D_SZ);
    };

    auto issue_load = [&](int j) {
        uint32_t mb  = mbar0 + (j % NS) * 8;
        uint32_t dst = buf0 + (uint32_t)(j % NS) * ROW_BYTES;
        asm volatile("mbarrier.arrive.expect_tx.shared.b64 _, [%0], %1;"
                     :: "r"(mb), "r"((uint32_t)ROW_BYTES) : "memory");
        asm volatile("cp.async.bulk.shared::cta.global.mbarrier::complete_tx::bytes "
                     "[%0], [%1], %2, [%3];"
                     :: "r"(dst), "l"(src_of(j)), "r"((uint32_t)ROW_BYTES), "r"(mb)
                     : "memory");
    };

    const int npro = m < LOOKAHEAD ? m : LOOKAHEAD;
    for (int j = 0; j < npro; j++) issue_load(j);

    for (int j = 0; j < m; j++) {
        const uint32_t mb     = mbar0 + (j % NS) * 8;
        const uint32_t buf    = buf0 + (uint32_t)(j % NS) * ROW_BYTES;
        const uint32_t parity = (uint32_t)((j / NS) & 1);

        uint32_t done;
        asm volatile(
            "{\n\t.reg .pred p;\n\t"
            "mbarrier.try_wait.parity.acquire.cta.shared::cta.b64 p, [%1], %2;\n\t"
            "selp.b32 %0, 1, 0, p;\n\t}"
            : "=r"(done) : "r"(mb), "r"(parity) : "memory");
        if (!done) {
            asm volatile(
                "{\n\t.reg .pred P1;\n\t"
                "W_%=:\n\t"
                "mbarrier.try_wait.parity.acquire.cta.shared::cta.b64 P1, [%0], %1, 0x989680;\n\t"
                "@P1 bra.uni D_%=;\n\t"
                "bra.uni W_%=;\n\t"
                "D_%=:\n\t}"
                :: "r"(mb), "r"(parity) : "memory");
        }

        char* dst = (char*)(out + (size_t)(t0 + s_list[j]) * D_SZ);
        asm volatile("cp.async.bulk.global.shared::cta.bulk_group [%0], [%1], %2;"
                     :: "l"(dst), "r"(buf), "r"((uint32_t)ROW_BYTES) : "memory");
        asm volatile("cp.async.bulk.commit_group;" ::: "memory");

        if (j + LOOKAHEAD < m) {
            asm volatile("cp.async.bulk.wait_group.read 2;" ::: "memory");
            issue_load(j + LOOKAHEAD);
        }
    }
    asm volatile("cp.async.bulk.wait_group 0;" ::: "memory");
}

// ---------------------------------------------------------------------------
// flatten: load per-block counts, prefix, scatter into s_flat. Returns cnt.
// ---------------------------------------------------------------------------
__device__ __forceinline__ int flatten_list(int* s_bcnt, int* s_off,
                                            int* s_flat, int* s_cnt)
{
    const int tid = threadIdx.x;
    for (int b = tid; b < GRID_GATHER; b += THREADS) s_bcnt[b] = g_bcnt[b];
    __syncthreads();
    if (tid == 0) {
        int c = 0;
        for (int b = 0; b < GRID_GATHER; b++) { s_off[b] = c; c += s_bcnt[b]; }
        *s_cnt = c < MAXS ? c : MAXS;
    }
    __syncthreads();
    int cnt = *s_cnt;
    if (cnt > 0) {
        for (int b = tid; b < GRID_GATHER; b += THREADS) {
            int k = s_bcnt[b], o = s_off[b];
            for (int j = 0; j < k; j++)
                if (o + j < MAXS) s_flat[o + j] = g_list[b * TOK_PER_BLK + j];
        }
    }
    __syncthreads();
    return cnt;
}

// ---------------------------------------------------------------------------
// K2: partial projections. grid (10 col-chunks, 8 k-segments) = 80 blocks.
// Each block: up to 8 tokens per register pass; fc_w read is 256B/warp
// contiguous, unroll-8 -> deep MLP; fc_w streams chip-wide at ~4-5 TB/s.
// ---------------------------------------------------------------------------
__global__ __launch_bounds__(THREADS)
void vx_partial_kernel(const int*   __restrict__ text,
                       const float* __restrict__ vis,    // [B*T, VIS_DIM]
                       const float* __restrict__ fc_w)   // [VIS_DIM, D]
{
    __shared__ int   s_bcnt[GRID_GATHER], s_off[GRID_GATHER];
    __shared__ int   s_flat[MAXS], s_cnt;
    __shared__ float s_vis[MAXT][VIS_DIM];               // 24 KB

    const int cnt = flatten_list(s_bcnt, s_off, s_flat, &s_cnt);
    if (cnt == 0) return;

    const int chunk = blockIdx.x;          // 0..9
    const int kseg  = blockIdx.y;          // 0..7
    const int tid   = threadIdx.x;
    const int col   = chunk * CCOLS + tid * 2;
    const int k0    = kseg * KSEG2;

    for (int g0 = 0; g0 < cnt; g0 += MAXT) {
        const int nt = min(MAXT, cnt - g0);

        // stage nt vision rows (zero unused rows so unguarded FMA is safe)
        for (int idx = tid; idx < MAXT * VIS_DIM; idx += THREADS) {
            int t = idx / VIS_DIM, i = idx % VIS_DIM;
            float val = 0.f;
            if (t < nt) {
                int tok = s_flat[g0 + t];
                int id  = __ldg(&text[tok]);
                int tv  = id - N_SHARED;
                if (tv > T_SZ - 1) tv = T_SZ - 1;
                if (tv < 0)        tv = 0;
                int b = tok >> 11;                       // / S_SZ
                val = __ldg(&vis[((size_t)(b * T_SZ + tv)) * VIS_DIM + i]);
            }
            s_vis[t][i] = val;
        }
        __syncthreads();

        float2 acc[MAXT];
        #pragma unroll
        for (int t = 0; t < MAXT; t++) acc[t] = make_float2(0.f, 0.f);

        const float2* w2 = (const float2*)(fc_w + col);  // stride D/2 float2
        #pragma unroll 8
        for (int k = 0; k < KSEG2; k++) {
            float2 w = __ldg(&w2[(size_t)(k0 + k) * (D_SZ / 2)]);
            #pragma unroll
            for (int t = 0; t < MAXT; t++) {
                float a = s_vis[t][k0 + k];
                acc[t].x = fmaf(a, w.x, acc[t].x);
                acc[t].y = fmaf(a, w.y, acc[t].y);
            }
        }

        for (int t = 0; t < nt; t++)
            *(float2*)(g_part + ((size_t)kseg * MAXS + (g0 + t)) * D_SZ + col)
                = acc[t];
        __syncthreads();                                 // before s_vis reuse
    }
}

// ---------------------------------------------------------------------------
// K3: combine partials + bias -> out. grid (10 chunks x 8 slots) = 80 blocks.
// ---------------------------------------------------------------------------
__global__ __launch_bounds__(THREADS)
void vx_combine_kernel(const float* __restrict__ fc_b,
                       float*       __restrict__ out)
{
    __shared__ int s_bcnt[GRID_GATHER], s_off[GRID_GATHER];
    __shared__ int s_flat[MAXS], s_cnt;

    const int cnt = flatten_list(s_bcnt, s_off, s_flat, &s_cnt);
    if (cnt == 0) return;

    const int chunk = blockIdx.x / K3_SLOTS;
    const int slot  = blockIdx.x % K3_SLOTS;
    const int tid   = threadIdx.x;
    const int col   = chunk * CCOLS + tid * 2;

    float2 bias = *(const float2*)(fc_b + col);

    for (int s = slot; s < cnt; s += K3_SLOTS) {
        float2 r = bias;
        #pragma unroll
        for (int ks = 0; ks < KS; ks++) {
            float2 p = *(const float2*)(g_part + ((size_t)ks * MAXS + s) * D_SZ + col);
            r.x += p.x;
            r.y += p.y;
        }
        int tok = s_flat[s];
        *(float2*)(out + (size_t)tok * D_SZ + col) = r;
    }
}

extern "C" void kernel_launch(void* const* d_in, const int* in_sizes, int n_in,
                              void* d_out, int out_size)
{
    const int*   text   = (const int*)  d_in[0];  // [B,S] int32
    const float* vis    = (const float*)d_in[1];  // [B,T,VIS_DIM]
    const float* weight = (const float*)d_in[2];  // [V,D]
    const float* fig    = (const float*)d_in[3];  // [2,D]
    const float* fc_w   = (const float*)d_in[4];  // [VIS_DIM,D]
    const float* fc_b   = (const float*)d_in[5];  // [D]
    float*       out    = (float*)d_out;

    cudaFuncSetAttribute(gather_tma_kernel,
                         cudaFuncAttributeMaxDynamicSharedMemorySize, SMEM_BYTES);
    gather_tma_kernel<<<GRID_GATHER, THREADS, SMEM_BYTES>>>(text, weight, fig, out);

    vx_partial_kernel<<<dim3(NCH2, KS), THREADS>>>(text, vis, fc_w);
    vx_combine_kernel<<<NCH2 * K3_SLOTS, THREADS>>>(fc_b, out);
}